// round 15
// baseline (speedup 1.0000x reference)
#include <cuda_runtime.h>
#include <cuda_bf16.h>
#include <cuda_fp16.h>
#include <math.h>
#include <stdint.h>

#define S_LEN  2048
#define NHEAD  16
#define DHEAD  64
#define BATCH  2
#define DMODEL 1024
#define BH     (BATCH*NHEAD)
#define NPOS   1024

// ---------------- static scratch ----------------
__device__ float g_c2p[BH*NPOS];
__device__ float g_bias[3072];
__device__ __align__(16) __nv_bfloat16 g_p2cb[(size_t)BH*NPOS*S_LEN];  // bf16 [bh][u][j]

__device__ __align__(16) __nv_bfloat16 g_x2 [(size_t)4096*2048];   // fp16 split
__device__ __align__(16) __nv_bfloat16 g_w2 [(size_t)3072*2048];   // fp16 split
__device__ __align__(16) __nv_bfloat16 g_wc2[(size_t)1024*2048];   // fp16 split
__device__ __align__(16) __nv_bfloat16 g_pt2[(size_t)1024*128];    // fp16 split
__device__ __align__(16) __nv_bfloat16 g_ao2[(size_t)4096*2048];   // fp16 split
// q/k/v fp16 split planes [bh][s][hi 64 | lo 64]; q pre-scaled by 0.125
__device__ __align__(16) __nv_bfloat16 g_q2 [(size_t)BH*S_LEN*128];
__device__ __align__(16) __nv_bfloat16 g_k2 [(size_t)BH*S_LEN*128];
__device__ __align__(16) __nv_bfloat16 g_v2 [(size_t)BH*S_LEN*128];

// ---------------- helpers ----------------
__device__ __forceinline__ void mma_h(float* d, const uint32_t* a, uint32_t b0, uint32_t b1) {
    asm volatile(
        "mma.sync.aligned.m16n8k16.row.col.f32.f16.f16.f32 "
        "{%0,%1,%2,%3}, {%4,%5,%6,%7}, {%8,%9}, {%0,%1,%2,%3};"
        : "+f"(d[0]), "+f"(d[1]), "+f"(d[2]), "+f"(d[3])
        : "r"(a[0]), "r"(a[1]), "r"(a[2]), "r"(a[3]), "r"(b0), "r"(b1));
}
__device__ __forceinline__ void ldsm_x4(uint32_t* r, uint32_t a) {
    asm volatile("ldmatrix.sync.aligned.m8n8.x4.shared.b16 {%0,%1,%2,%3}, [%4];"
                 : "=r"(r[0]), "=r"(r[1]), "=r"(r[2]), "=r"(r[3]) : "r"(a));
}
__device__ __forceinline__ void ldsm_x4_t(uint32_t* r, uint32_t a) {
    asm volatile("ldmatrix.sync.aligned.m8n8.x4.trans.shared.b16 {%0,%1,%2,%3}, [%4];"
                 : "=r"(r[0]), "=r"(r[1]), "=r"(r[2]), "=r"(r[3]) : "r"(a));
}
__device__ __forceinline__ uint32_t smem_u32(const void* p) {
    uint32_t a;
    asm("{ .reg .u64 t; cvta.to.shared.u64 t, %1; cvt.u32.u64 %0, t; }" : "=r"(a) : "l"(p));
    return a;
}
__device__ __forceinline__ uint32_t pack_bf2(__nv_bfloat16 a, __nv_bfloat16 b) {
    return (uint32_t)__bfloat16_as_ushort(a) | ((uint32_t)__bfloat16_as_ushort(b) << 16);
}
__device__ __forceinline__ uint32_t pack_h2(float a, float b) {
    __half2 h = __floats2half2_rn(a, b);
    return *(uint32_t*)&h;
}
__device__ __forceinline__ void split_pack_h(float x0, float x1, uint32_t& h, uint32_t& l) {
    __half h0 = __float2half_rn(x0), h1 = __float2half_rn(x1);
    h = (uint32_t)__half_as_ushort(h0) | ((uint32_t)__half_as_ushort(h1) << 16);
    l = (uint32_t)__half_as_ushort(__float2half_rn(x0 - __half2float(h0))) |
        ((uint32_t)__half_as_ushort(__float2half_rn(x1 - __half2float(h1))) << 16);
}

// ---------------- fp16 split conversion ----------------
__global__ void __launch_bounds__(256) cvt_split(
    const float* __restrict__ src, __nv_bfloat16* __restrict__ dst,
    int kshift, long long n4)
{
    long long i = (long long)blockIdx.x * 256 + threadIdx.x;
    if (i >= n4) return;
    long long e = i << 2;
    const int K = 1 << kshift;
    long long row = e >> kshift;
    int col = (int)(e & (K - 1));
    float4 v = *(const float4*)(src + e);
    uint32_t h01, l01, h23, l23;
    split_pack_h(v.x, v.y, h01, l01);
    split_pack_h(v.z, v.w, h23, l23);
    __nv_bfloat16* drow = dst + (row << (kshift + 1));
    *(uint2*)(drow + col)     = make_uint2(h01, h23);
    *(uint2*)(drow + K + col) = make_uint2(l01, l23);
}

__global__ void bias_concat(const float* __restrict__ bq, const float* __restrict__ bk,
                            const float* __restrict__ bv)
{
    int i = blockIdx.x * 256 + threadIdx.x;
    if (i >= 3072) return;
    g_bias[i] = (i < 1024) ? bq[i] : (i < 2048) ? bk[i - 1024] : bv[i - 2048];
}

// ---------------- HMMA GEMM, fp16 splits ----------------
// TERMS==3: ah*bh + al*bh + ah*bl (r-major segment schedule).
// TERMS==2: ah*bh + al*bh (B hi plane only).
// mode 0: fp32 C.  mode 1: qkv scatter+bias -> fp16 split planes.  mode 2: bf16 C.
#define GP 72
#define STAGE (128*GP)
template<int TERMS>
__global__ void __launch_bounds__(256, 2) hmma_gemm(
    const __nv_bfloat16* __restrict__ A2, int lda2, long long sA,
    const __nv_bfloat16* __restrict__ B2, int ldb2, long long sB,
    void* __restrict__ Cv, int ldc, long long sC, int K, int mode)
{
    extern __shared__ __nv_bfloat16 sb[];
    const int tid  = threadIdx.x;
    const int wid  = tid >> 5;
    const int lane = tid & 31;
    const int g    = lane >> 2;
    const int tig  = lane & 3;
    const int wm   = wid >> 2;
    const int wn   = wid & 3;

    const int n0 = blockIdx.x << 7;
    const int m0 = blockIdx.y << 7;

    A2 += (long long)blockIdx.z * sA + (size_t)m0 * lda2;
    B2 += (long long)blockIdx.z * sB + (size_t)n0 * ldb2;

    const int ns = TERMS * (K >> 6);
    const int lrow = tid >> 3;
    const int lch  = tid & 7;

    __nv_bfloat16* SA[2] = { sb,             sb + STAGE };
    __nv_bfloat16* SB[2] = { sb + 2*STAGE,   sb + 3*STAGE };

    float d[4][4][4];
    #pragma unroll
    for (int a = 0; a < 4; a++)
        #pragma unroll
        for (int b = 0; b < 4; b++)
            #pragma unroll
            for (int c = 0; c < 4; c++) d[a][b][c] = 0.f;

    #pragma unroll
    for (int i = 0; i < 4; i++) {
        int row = lrow + (i << 5);
        *(uint4*)(SA[0] + row*GP + (lch << 3)) = *(const uint4*)(A2 + (size_t)row*lda2 + (lch << 3));
        *(uint4*)(SB[0] + row*GP + (lch << 3)) = *(const uint4*)(B2 + (size_t)row*ldb2 + (lch << 3));
    }
    __syncthreads();

    for (int t = 0; t < ns; t++) {
        const int r   = t / TERMS;
        const int seg = t - TERMS*r;
        const int q   = r & 1;

        // prefetch for stage t+1
        uint4 ra[4], rb[4];
        int nseg = -1, nq = 0;
        if (t + 1 < ns) {
            int t1 = t + 1;
            int r1 = t1 / TERMS; nseg = t1 - TERMS*r1; nq = r1 & 1;
            if (nseg == 0) {
                const __nv_bfloat16* ga = A2 + (r1 << 6);
                const __nv_bfloat16* gb = B2 + (r1 << 6);
                #pragma unroll
                for (int i = 0; i < 4; i++) {
                    int row = lrow + (i << 5);
                    ra[i] = *(const uint4*)(ga + (size_t)row*lda2 + (lch << 3));
                    rb[i] = *(const uint4*)(gb + (size_t)row*ldb2 + (lch << 3));
                }
            } else if (nseg == 1) {
                // TERMS==2: Al(r1).  TERMS==3: Bl(r1).
                if (TERMS == 2) {
                    const __nv_bfloat16* ga = A2 + K + (r1 << 6);
                    #pragma unroll
                    for (int i = 0; i < 4; i++) {
                        int row = lrow + (i << 5);
                        ra[i] = *(const uint4*)(ga + (size_t)row*lda2 + (lch << 3));
                    }
                } else {
                    const __nv_bfloat16* gb = B2 + K + (r1 << 6);
                    #pragma unroll
                    for (int i = 0; i < 4; i++) {
                        int row = lrow + (i << 5);
                        rb[i] = *(const uint4*)(gb + (size_t)row*ldb2 + (lch << 3));
                    }
                }
            } else {  // TERMS==3 only: Al(r1)
                const __nv_bfloat16* ga = A2 + K + (r1 << 6);
                #pragma unroll
                for (int i = 0; i < 4; i++) {
                    int row = lrow + (i << 5);
                    ra[i] = *(const uint4*)(ga + (size_t)row*lda2 + (lch << 3));
                }
            }
        }

        const __nv_bfloat16* As;
        const __nv_bfloat16* Bs;
        if (TERMS == 2) {
            As = SA[seg ? (q ^ 1) : q];
            Bs = SB[q];
        } else {
            As = SA[(seg == 2) ? (q ^ 1) : q];
            Bs = SB[(seg == 1) ? (q ^ 1) : q];
        }
        #pragma unroll
        for (int kk = 0; kk < 4; kk++) {
            const int kc = (kk << 4) + (tig << 1);
            uint32_t af[4][4], bf[4][2];
            #pragma unroll
            for (int mt = 0; mt < 4; mt++) {
                const __nv_bfloat16* pa = As + (size_t)((wm << 6) + (mt << 4) + g)*GP + kc;
                af[mt][0] = *(const uint32_t*)(pa);
                af[mt][1] = *(const uint32_t*)(pa + 8*GP);
                af[mt][2] = *(const uint32_t*)(pa + 8);
                af[mt][3] = *(const uint32_t*)(pa + 8*GP + 8);
            }
            #pragma unroll
            for (int nt = 0; nt < 4; nt++) {
                const __nv_bfloat16* pb = Bs + (size_t)((wn << 5) + (nt << 3) + g)*GP + kc;
                bf[nt][0] = *(const uint32_t*)(pb);
                bf[nt][1] = *(const uint32_t*)(pb + 8);
            }
            #pragma unroll
            for (int mt = 0; mt < 4; mt++)
                #pragma unroll
                for (int nt = 0; nt < 4; nt++)
                    mma_h(d[mt][nt], af[mt], bf[nt][0], bf[nt][1]);
        }
        __syncthreads();
        if (t + 1 < ns) {
            if (nseg == 0) {
                __nv_bfloat16* dA = SA[nq];
                __nv_bfloat16* dB = SB[nq];
                #pragma unroll
                for (int i = 0; i < 4; i++) {
                    int row = lrow + (i << 5);
                    *(uint4*)(dA + row*GP + (lch << 3)) = ra[i];
                    *(uint4*)(dB + row*GP + (lch << 3)) = rb[i];
                }
            } else if (nseg == 1) {
                if (TERMS == 2) {
                    __nv_bfloat16* dA = SA[nq ^ 1];
                    #pragma unroll
                    for (int i = 0; i < 4; i++) {
                        int row = lrow + (i << 5);
                        *(uint4*)(dA + row*GP + (lch << 3)) = ra[i];
                    }
                } else {
                    __nv_bfloat16* dB = SB[nq ^ 1];
                    #pragma unroll
                    for (int i = 0; i < 4; i++) {
                        int row = lrow + (i << 5);
                        *(uint4*)(dB + row*GP + (lch << 3)) = rb[i];
                    }
                }
            } else {
                __nv_bfloat16* dA = SA[nq ^ 1];
                #pragma unroll
                for (int i = 0; i < 4; i++) {
                    int row = lrow + (i << 5);
                    *(uint4*)(dA + row*GP + (lch << 3)) = ra[i];
                }
            }
            __syncthreads();
        }
    }

    #pragma unroll
    for (int mt = 0; mt < 4; mt++) {
        #pragma unroll
        for (int nt = 0; nt < 4; nt++) {
            int n = n0 + (wn << 5) + (nt << 3) + (tig << 1);
            int m_lo = m0 + (wm << 6) + (mt << 4) + g;
            if (mode == 1) {
                const int w3 = n >> 10;
                __nv_bfloat16* tgt = (w3 == 0) ? g_q2 : (w3 == 1) ? g_k2 : g_v2;
                const float sc = (w3 == 0) ? 0.125f : 1.0f;
                float2 bb = *(const float2*)&g_bias[n];
                int h = (n & 1023) >> 6, d0 = n & 63;
                #pragma unroll
                for (int half = 0; half < 2; half++) {
                    int m = m_lo + half*8;
                    int b = m >> 11, s = m & 2047;
                    float x0 = (d[mt][nt][2*half]   + bb.x) * sc;
                    float x1 = (d[mt][nt][2*half+1] + bb.y) * sc;
                    uint32_t hh, ll;
                    split_pack_h(x0, x1, hh, ll);
                    size_t base = (((size_t)b*NHEAD + h)*S_LEN + s)*128 + d0;
                    *(uint32_t*)&tgt[base]      = hh;
                    *(uint32_t*)&tgt[base + 64] = ll;
                }
            } else if (mode == 2) {
                __nv_bfloat16* Cb = (__nv_bfloat16*)Cv + (long long)blockIdx.z * sC;
                *(uint32_t*)&Cb[(size_t)m_lo*ldc + n] =
                    pack_bf2(__float2bfloat16_rn(d[mt][nt][0]), __float2bfloat16_rn(d[mt][nt][1]));
                *(uint32_t*)&Cb[(size_t)(m_lo + 8)*ldc + n] =
                    pack_bf2(__float2bfloat16_rn(d[mt][nt][2]), __float2bfloat16_rn(d[mt][nt][3]));
            } else {
                float* C = (float*)Cv + (long long)blockIdx.z * sC;
                *(float2*)(C + (size_t)m_lo*ldc + n)       = make_float2(d[mt][nt][0], d[mt][nt][1]);
                *(float2*)(C + (size_t)(m_lo + 8)*ldc + n) = make_float2(d[mt][nt][2], d[mt][nt][3]);
            }
        }
    }
}

// ---------------- c2p table (q2 = fp16 split planes, q pre-scaled by 1/8) ----------------
__global__ void __launch_bounds__(256) c2p_kernel(const float* __restrict__ pt)
{
    const int bh = blockIdx.x;
    const __half* q2 = (const __half*)(g_q2 + (size_t)bh*S_LEN*128);
    __shared__ float part[256];
    __shared__ float qsum[64];
    const int tid = threadIdx.x;
    const int d = tid & 63, sg = tid >> 6;

    float acc = 0.f;
    for (int s = sg; s < S_LEN; s += 4) {
        const __half* row = q2 + (size_t)s*128;
        acc += __half2float(row[d]) + __half2float(row[64 + d]);
    }
    part[tid] = acc;
    __syncthreads();
    if (tid < 64) qsum[tid] = (part[tid] + part[tid+64] + part[tid+128] + part[tid+192]) * 8.0f;
    __syncthreads();

    const int u = (blockIdx.y << 8) + tid;
    float vsum = 0.f;
    #pragma unroll 16
    for (int dd = 0; dd < 64; dd++) vsum += qsum[dd] * pt[u*64 + dd];
    g_c2p[bh*NPOS + u] = vsum;
}

// ---------------- flash attention: fp16 HMMA, QK 2-term, PV 2-term ----------------
#define FGP 72
#define SQ_ELEMS (2*128*FGP)
#define FLASH_SMEM_BYTES (SQ_ELEMS*2 + (64*FGP)*2 + (2*64*FGP)*2 + 1024*4)  // 68608 B

__global__ void __launch_bounds__(256, 2) flash_attn()
{
    const int bh = blockIdx.y;
    const int i0 = blockIdx.x << 7;
    const __nv_bfloat16* q2 = g_q2 + (size_t)bh*S_LEN*128;
    const __nv_bfloat16* k2 = g_k2 + (size_t)bh*S_LEN*128;
    const __nv_bfloat16* v2 = g_v2 + (size_t)bh*S_LEN*128;
    const float* c2p = g_c2p + bh*NPOS;
    const __nv_bfloat16* p2cb = g_p2cb + (size_t)bh*NPOS*S_LEN;

    extern __shared__ __nv_bfloat16 smb[];
    __nv_bfloat16* sq   = smb;                  // Q planes; reused as p2c band
    __nv_bfloat16* stgb = smb;                  // [191][72] bf16 (alias)
    __nv_bfloat16* sk   = smb + SQ_ELEMS;       // K hi plane only
    __nv_bfloat16* sv   = sk + 64*FGP;          // V: 2 planes
    float* c2ps = (float*)(sv + 2*64*FGP);

    const uint32_t sq_u = smem_u32(sq);
    const uint32_t sk_u = smem_u32(sk);
    const uint32_t sv_u = smem_u32(sv);

    const int tid = threadIdx.x;
    const int wid = tid >> 5;
    const int lane = tid & 31;
    const int g = lane >> 2, tig = lane & 3;
    const int lro = ((lane >> 3) & 1) << 3;
    const int lr8 = lane & 7;
    const int lco = (lane >> 4) << 3;

    {
        int row = tid >> 1, half = tid & 1;
        const uint4* s4 = (const uint4*)(q2 + (size_t)(i0 + row)*128 + half*64);
        uint4* d4 = (uint4*)(sq + half*(128*FGP) + row*FGP);
        d4[0] = s4[0]; d4[1] = s4[1]; d4[2] = s4[2]; d4[3] = s4[3];
        d4[4] = s4[4]; d4[5] = s4[5]; d4[6] = s4[6]; d4[7] = s4[7];
    }
    for (int u = tid; u < NPOS; u += 256) c2ps[u] = c2p[u];
    __syncthreads();

    uint32_t qf[2][4][4];
    #pragma unroll
    for (int pl = 0; pl < 2; pl++)
        #pragma unroll
        for (int kc = 0; kc < 4; kc++)
            ldsm_x4(qf[pl][kc], sq_u + ((pl*128 + (wid << 4) + lro + lr8)*FGP + lco + kc*16)*2);

    float o[8][4];
    #pragma unroll
    for (int nt = 0; nt < 8; nt++)
        #pragma unroll
        for (int e = 0; e < 4; e++) o[nt][e] = 0.f;
    float mx[2] = {-1e30f, -1e30f}, lsum[2] = {0.f, 0.f};

    const int rl0 = (wid << 4) + g;

    for (int j0 = 0; j0 < S_LEN; j0 += 64) {
        __syncthreads();
        for (int idx = tid; idx < 512; idx += 256) {
            int row = idx >> 3, ch = (idx & 7) << 3;
            *(uint4*)(sk + row*FGP + ch) = *(const uint4*)(k2 + (size_t)(j0 + row)*128 + ch);
        }
        for (int idx = tid; idx < 1024; idx += 256) {
            int p = idx >> 9, rem = idx & 511;
            int row = rem >> 3, ch = (rem & 7) << 3;
            *(uint4*)(sv + (p*64 + row)*FGP + ch) =
                *(const uint4*)(v2 + (size_t)(j0 + row)*128 + p*64 + ch);
        }
        const int u_lo = 2369 - i0 - j0;
        for (int idx = tid; idx < 191*8; idx += 256) {
            int su = idx >> 3, c8 = (idx & 7) << 3;
            int u = min(max(u_lo + su, 0), NPOS - 1);
            *(uint4*)&stgb[su*FGP + c8] = *(const uint4*)&p2cb[(size_t)u*S_LEN + j0 + c8];
        }
        __syncthreads();

        float s[8][4];
        #pragma unroll
        for (int nt = 0; nt < 8; nt++)
            #pragma unroll
            for (int e = 0; e < 4; e++) s[nt][e] = 0.f;

        #pragma unroll
        for (int kc = 0; kc < 4; kc++) {
            #pragma unroll
            for (int t = 0; t < 4; t++) {
                uint32_t kf[4];
                ldsm_x4(kf, sk_u + (((t << 4) + lro + lr8)*FGP + lco + kc*16)*2);
                mma_h(s[2*t],   qf[0][kc], kf[0], kf[2]);
                mma_h(s[2*t+1], qf[0][kc], kf[1], kf[3]);
                mma_h(s[2*t],   qf[1][kc], kf[0], kf[2]);
                mma_h(s[2*t+1], qf[1][kc], kf[1], kf[3]);
            }
        }

        #pragma unroll
        for (int rr = 0; rr < 2; rr++) {
            int rl = rl0 + rr*8;
            int r  = i0 + rl;
            #pragma unroll
            for (int nt = 0; nt < 8; nt++)
                #pragma unroll
                for (int e = 0; e < 2; e++) {
                    int cl = (nt << 3) + (tig << 1) + e;
                    int ic = min(max(r - (j0 + cl) + 512, 0), NPOS - 1);
                    s[nt][rr*2 + e] += c2ps[ic] + __bfloat162float(stgb[(190 - rl - cl)*FGP + cl]);
                }
        }

        float fac[2];
        #pragma unroll
        for (int rr = 0; rr < 2; rr++) {
            float rm = -1e30f;
            #pragma unroll
            for (int nt = 0; nt < 8; nt++)
                rm = fmaxf(rm, fmaxf(s[nt][rr*2], s[nt][rr*2+1]));
            rm = fmaxf(rm, __shfl_xor_sync(0xffffffffu, rm, 1));
            rm = fmaxf(rm, __shfl_xor_sync(0xffffffffu, rm, 2));
            float mn = fmaxf(mx[rr], rm);
            fac[rr] = __expf(mx[rr] - mn);
            mx[rr] = mn;
            float rs = 0.f;
            #pragma unroll
            for (int nt = 0; nt < 8; nt++) {
                s[nt][rr*2]   = __expf(s[nt][rr*2]   - mn);
                s[nt][rr*2+1] = __expf(s[nt][rr*2+1] - mn);
                rs += s[nt][rr*2] + s[nt][rr*2+1];
            }
            rs += __shfl_xor_sync(0xffffffffu, rs, 1);
            rs += __shfl_xor_sync(0xffffffffu, rs, 2);
            lsum[rr] = lsum[rr]*fac[rr] + rs;
        }
        #pragma unroll
        for (int nt = 0; nt < 8; nt++) {
            o[nt][0] *= fac[0]; o[nt][1] *= fac[0];
            o[nt][2] *= fac[1]; o[nt][3] *= fac[1];
        }

        #pragma unroll
        for (int kc = 0; kc < 4; kc++) {
            uint32_t ph[4];
            ph[0] = pack_h2(s[2*kc][0],   s[2*kc][1]);
            ph[1] = pack_h2(s[2*kc][2],   s[2*kc][3]);
            ph[2] = pack_h2(s[2*kc+1][0], s[2*kc+1][1]);
            ph[3] = pack_h2(s[2*kc+1][2], s[2*kc+1][3]);
            #pragma unroll
            for (int nd = 0; nd < 4; nd++) {
                uint32_t vf[4], vl[4];
                ldsm_x4_t(vf, sv_u + (((kc << 4) + lro + lr8)*FGP + (nd << 4) + lco)*2);
                ldsm_x4_t(vl, sv_u + ((64 + (kc << 4) + lro + lr8)*FGP + (nd << 4) + lco)*2);
                mma_h(o[2*nd],   ph, vf[0], vf[1]);
                mma_h(o[2*nd+1], ph, vf[2], vf[3]);
                mma_h(o[2*nd],   ph, vl[0], vl[1]);
                mma_h(o[2*nd+1], ph, vl[2], vl[3]);
            }
        }
    }

    // ---- epilogue: fp16 split planes -> g_ao2 ----
    const int b = bh >> 4, h = bh & 15;
    #pragma unroll
    for (int rr = 0; rr < 2; rr++) {
        int m = b*S_LEN + i0 + rl0 + rr*8;
        float inv = 1.0f / lsum[rr];
        __nv_bfloat16* dst = g_ao2 + (size_t)m*2048 + h*64;
        #pragma unroll
        for (int nt = 0; nt < 8; nt++) {
            int d0 = (nt << 3) + (tig << 1);
            uint32_t hh, ll;
            split_pack_h(o[nt][rr*2]*inv, o[nt][rr*2+1]*inv, hh, ll);
            *(uint32_t*)&dst[d0]        = hh;
            *(uint32_t*)&dst[1024 + d0] = ll;
        }
    }
}

// ---------------- launch ----------------
extern "C" void kernel_launch(void* const* d_in, const int* in_sizes, int n_in,
                              void* d_out, int out_size)
{
    const float* hidden = (const float*)d_in[0];
    const float* Wq = (const float*)d_in[1];
    const float* bq = (const float*)d_in[2];
    const float* Wk = (const float*)d_in[3];
    const float* bk = (const float*)d_in[4];
    const float* Wv = (const float*)d_in[5];
    const float* bv = (const float*)d_in[6];
    const float* Wc = (const float*)d_in[7];
    const float* pt = (const float*)d_in[8];
    float* out = (float*)d_out;

    __nv_bfloat16 *px2, *pw2, *pwc2, *ppt2, *pk2, *pao2, *pp2cb;
    cudaGetSymbolAddress((void**)&pp2cb, g_p2cb);
    cudaGetSymbolAddress((void**)&px2,  g_x2);
    cudaGetSymbolAddress((void**)&pw2,  g_w2);
    cudaGetSymbolAddress((void**)&pwc2, g_wc2);
    cudaGetSymbolAddress((void**)&ppt2, g_pt2);
    cudaGetSymbolAddress((void**)&pk2,  g_k2);
    cudaGetSymbolAddress((void**)&pao2, g_ao2);

    const int gemm_smem = 4 * STAGE * (int)sizeof(__nv_bfloat16);
    static int once = 0;
    if (!once) {
        cudaFuncSetAttribute(flash_attn, cudaFuncAttributeMaxDynamicSharedMemorySize, FLASH_SMEM_BYTES);
        cudaFuncSetAttribute(hmma_gemm<2>, cudaFuncAttributeMaxDynamicSharedMemorySize, gemm_smem);
        cudaFuncSetAttribute(hmma_gemm<3>, cudaFuncAttributeMaxDynamicSharedMemorySize, gemm_smem);
        once = 1;
    }

    cvt_split<<<4096, 256>>>(hidden, px2, 10, (long long)4096*1024/4);
    cvt_split<<<1024, 256>>>(Wq, pw2,                     10, (long long)1024*1024/4);
    cvt_split<<<1024, 256>>>(Wk, pw2 + (size_t)1024*2048, 10, (long long)1024*1024/4);
    cvt_split<<<1024, 256>>>(Wv, pw2 + (size_t)2048*2048, 10, (long long)1024*1024/4);
    cvt_split<<<1024, 256>>>(Wc, pwc2,                    10, (long long)1024*1024/4);
    cvt_split<<<64,   256>>>(pt, ppt2,                     6, (long long)1024*64/4);
    bias_concat<<<12, 256>>>(bq, bk, bv);

    // QKV (fp16 2-term) -> fp16 split planes
    hmma_gemm<2><<<dim3(24, 32, 1), 256, gemm_smem>>>(
        px2, 2048, 0, pw2, 2048, 0, nullptr, 0, 0, 1024, 1);

    c2p_kernel<<<dim3(BH, 4), 256>>>(pt);

    // P2C (fp16 3-term) -> bf16
    hmma_gemm<3><<<dim3(16, 8, BH), 256, gemm_smem>>>(
        ppt2, 128, 0, pk2, 128, (long long)S_LEN*128,
        pp2cb, S_LEN, (long long)NPOS*S_LEN, 64, 2);

    flash_attn<<<dim3(S_LEN/128, BH), 256, FLASH_SMEM_BYTES>>>();

    // c_proj (fp16 2-term)
    hmma_gemm<2><<<dim3(8, 32, 1), 256, gemm_smem>>>(
        pao2, 2048, 0, pwc2, 2048, 0, out, DMODEL, 0, 1024, 0);
}

// round 16
// speedup vs baseline: 1.3871x; 1.3871x over previous
#include <cuda_runtime.h>
#include <cuda_bf16.h>
#include <cuda_fp16.h>
#include <math.h>
#include <stdint.h>

#define S_LEN  2048
#define NHEAD  16
#define DHEAD  64
#define BATCH  2
#define DMODEL 1024
#define BH     (BATCH*NHEAD)
#define NPOS   1024

// ---------------- static scratch ----------------
__device__ float g_c2p[BH*NPOS];
__device__ float g_bias[3072];
__device__ __align__(16) __nv_bfloat16 g_p2cb[(size_t)BH*NPOS*S_LEN];  // bf16 [bh][u][j]

__device__ __align__(16) __nv_bfloat16 g_x2 [(size_t)4096*2048];   // bf16 split
__device__ __align__(16) __nv_bfloat16 g_w2 [(size_t)3072*2048];   // bf16 split
__device__ __align__(16) __nv_bfloat16 g_wc2[(size_t)1024*2048];   // bf16 split
__device__ __align__(16) __nv_bfloat16 g_pt2[(size_t)1024*128];    // fp16 split (bits)
__device__ __align__(16) __nv_bfloat16 g_ao2[(size_t)4096*2048];   // bf16 split
// q/k/v fp16 split planes [bh][s][hi 64 | lo 64]; q pre-scaled by 0.125
__device__ __align__(16) __nv_bfloat16 g_q2 [(size_t)BH*S_LEN*128];
__device__ __align__(16) __nv_bfloat16 g_k2 [(size_t)BH*S_LEN*128];
__device__ __align__(16) __nv_bfloat16 g_v2 [(size_t)BH*S_LEN*128];

// ---------------- helpers ----------------
__device__ __forceinline__ void mma_bf(float* d, const uint32_t* a, uint32_t b0, uint32_t b1) {
    asm volatile(
        "mma.sync.aligned.m16n8k16.row.col.f32.bf16.bf16.f32 "
        "{%0,%1,%2,%3}, {%4,%5,%6,%7}, {%8,%9}, {%0,%1,%2,%3};"
        : "+f"(d[0]), "+f"(d[1]), "+f"(d[2]), "+f"(d[3])
        : "r"(a[0]), "r"(a[1]), "r"(a[2]), "r"(a[3]), "r"(b0), "r"(b1));
}
__device__ __forceinline__ void mma_h(float* d, const uint32_t* a, uint32_t b0, uint32_t b1) {
    asm volatile(
        "mma.sync.aligned.m16n8k16.row.col.f32.f16.f16.f32 "
        "{%0,%1,%2,%3}, {%4,%5,%6,%7}, {%8,%9}, {%0,%1,%2,%3};"
        : "+f"(d[0]), "+f"(d[1]), "+f"(d[2]), "+f"(d[3])
        : "r"(a[0]), "r"(a[1]), "r"(a[2]), "r"(a[3]), "r"(b0), "r"(b1));
}
__device__ __forceinline__ void ldsm_x4(uint32_t* r, uint32_t a) {
    asm volatile("ldmatrix.sync.aligned.m8n8.x4.shared.b16 {%0,%1,%2,%3}, [%4];"
                 : "=r"(r[0]), "=r"(r[1]), "=r"(r[2]), "=r"(r[3]) : "r"(a));
}
__device__ __forceinline__ void ldsm_x4_t(uint32_t* r, uint32_t a) {
    asm volatile("ldmatrix.sync.aligned.m8n8.x4.trans.shared.b16 {%0,%1,%2,%3}, [%4];"
                 : "=r"(r[0]), "=r"(r[1]), "=r"(r[2]), "=r"(r[3]) : "r"(a));
}
__device__ __forceinline__ uint32_t smem_u32(const void* p) {
    uint32_t a;
    asm("{ .reg .u64 t; cvta.to.shared.u64 t, %1; cvt.u32.u64 %0, t; }" : "=r"(a) : "l"(p));
    return a;
}
__device__ __forceinline__ uint32_t pack_bf2(__nv_bfloat16 a, __nv_bfloat16 b) {
    return (uint32_t)__bfloat16_as_ushort(a) | ((uint32_t)__bfloat16_as_ushort(b) << 16);
}
__device__ __forceinline__ void split_pack(float x0, float x1, uint32_t& h, uint32_t& l) {
    __nv_bfloat16 h0 = __float2bfloat16_rn(x0), h1 = __float2bfloat16_rn(x1);
    h = pack_bf2(h0, h1);
    l = pack_bf2(__float2bfloat16_rn(x0 - __bfloat162float(h0)),
                 __float2bfloat16_rn(x1 - __bfloat162float(h1)));
}
__device__ __forceinline__ uint32_t pack_h2(float a, float b) {
    __half2 h = __floats2half2_rn(a, b);
    return *(uint32_t*)&h;
}
__device__ __forceinline__ void split_pack_h(float x0, float x1, uint32_t& h, uint32_t& l) {
    __half h0 = __float2half_rn(x0), h1 = __float2half_rn(x1);
    h = (uint32_t)__half_as_ushort(h0) | ((uint32_t)__half_as_ushort(h1) << 16);
    l = (uint32_t)__half_as_ushort(__float2half_rn(x0 - __half2float(h0))) |
        ((uint32_t)__half_as_ushort(__float2half_rn(x1 - __half2float(h1))) << 16);
}

// ---------------- split conversion (bf16 or fp16) ----------------
__global__ void __launch_bounds__(256) cvt_split(
    const float* __restrict__ src, __nv_bfloat16* __restrict__ dst,
    int kshift, long long n4, int use_f16)
{
    long long i = (long long)blockIdx.x * 256 + threadIdx.x;
    if (i >= n4) return;
    long long e = i << 2;
    const int K = 1 << kshift;
    long long row = e >> kshift;
    int col = (int)(e & (K - 1));
    float4 v = *(const float4*)(src + e);
    uint32_t h01, l01, h23, l23;
    if (use_f16) {
        split_pack_h(v.x, v.y, h01, l01);
        split_pack_h(v.z, v.w, h23, l23);
    } else {
        split_pack(v.x, v.y, h01, l01);
        split_pack(v.z, v.w, h23, l23);
    }
    __nv_bfloat16* drow = dst + (row << (kshift + 1));
    *(uint2*)(drow + col)     = make_uint2(h01, h23);
    *(uint2*)(drow + K + col) = make_uint2(l01, l23);
}

__global__ void bias_concat(const float* __restrict__ bq, const float* __restrict__ bk,
                            const float* __restrict__ bv)
{
    int i = blockIdx.x * 256 + threadIdx.x;
    if (i >= 3072) return;
    g_bias[i] = (i < 1024) ? bq[i] : (i < 2048) ? bk[i - 1024] : bv[i - 2048];
}

// ---------------- HMMA GEMM (3-term split, r-major segment schedule) ----------------
// F16: operands are fp16 splits; else bf16 splits.
// mode 0: fp32 C.  mode 1: qkv scatter+bias -> FP16 split planes.  mode 2: bf16 C.
#define GP 72
#define STAGE (128*GP)
template<bool F16>
__global__ void __launch_bounds__(256, 2) hmma_gemm(
    const __nv_bfloat16* __restrict__ A2, int lda2, long long sA,
    const __nv_bfloat16* __restrict__ B2, int ldb2, long long sB,
    void* __restrict__ Cv, int ldc, long long sC, int K, int mode)
{
    extern __shared__ __nv_bfloat16 sb[];
    const int tid  = threadIdx.x;
    const int wid  = tid >> 5;
    const int lane = tid & 31;
    const int g    = lane >> 2;
    const int tig  = lane & 3;
    const int wm   = wid >> 2;
    const int wn   = wid & 3;

    const int n0 = blockIdx.x << 7;
    const int m0 = blockIdx.y << 7;

    A2 += (long long)blockIdx.z * sA + (size_t)m0 * lda2;
    B2 += (long long)blockIdx.z * sB + (size_t)n0 * ldb2;

    const int ns = 3 * (K >> 6);
    const int lrow = tid >> 3;
    const int lch  = tid & 7;

    __nv_bfloat16* SA[2] = { sb,             sb + STAGE };
    __nv_bfloat16* SB[2] = { sb + 2*STAGE,   sb + 3*STAGE };

    float d[4][4][4];
    #pragma unroll
    for (int a = 0; a < 4; a++)
        #pragma unroll
        for (int b = 0; b < 4; b++)
            #pragma unroll
            for (int c = 0; c < 4; c++) d[a][b][c] = 0.f;

    #pragma unroll
    for (int i = 0; i < 4; i++) {
        int row = lrow + (i << 5);
        *(uint4*)(SA[0] + row*GP + (lch << 3)) = *(const uint4*)(A2 + (size_t)row*lda2 + (lch << 3));
        *(uint4*)(SB[0] + row*GP + (lch << 3)) = *(const uint4*)(B2 + (size_t)row*ldb2 + (lch << 3));
    }
    __syncthreads();

    for (int t = 0; t < ns; t++) {
        const int r   = t / 3;
        const int seg = t - 3*r;
        const int q   = r & 1;

        uint4 ra[4], rb[4];
        int nseg = -1, nq = 0;
        if (t + 1 < ns) {
            int t1 = t + 1;
            int r1 = t1 / 3; nseg = t1 - 3*r1; nq = r1 & 1;
            if (nseg == 0) {
                const __nv_bfloat16* ga = A2 + (r1 << 6);
                const __nv_bfloat16* gb = B2 + (r1 << 6);
                #pragma unroll
                for (int i = 0; i < 4; i++) {
                    int row = lrow + (i << 5);
                    ra[i] = *(const uint4*)(ga + (size_t)row*lda2 + (lch << 3));
                    rb[i] = *(const uint4*)(gb + (size_t)row*ldb2 + (lch << 3));
                }
            } else if (nseg == 1) {
                const __nv_bfloat16* gb = B2 + K + (r1 << 6);
                #pragma unroll
                for (int i = 0; i < 4; i++) {
                    int row = lrow + (i << 5);
                    rb[i] = *(const uint4*)(gb + (size_t)row*ldb2 + (lch << 3));
                }
            } else {
                const __nv_bfloat16* ga = A2 + K + (r1 << 6);
                #pragma unroll
                for (int i = 0; i < 4; i++) {
                    int row = lrow + (i << 5);
                    ra[i] = *(const uint4*)(ga + (size_t)row*lda2 + (lch << 3));
                }
            }
        }

        const __nv_bfloat16* As = SA[(seg == 2) ? (q ^ 1) : q];
        const __nv_bfloat16* Bs = SB[(seg == 1) ? (q ^ 1) : q];
        #pragma unroll
        for (int kk = 0; kk < 4; kk++) {
            const int kc = (kk << 4) + (tig << 1);
            uint32_t af[4][4], bf[4][2];
            #pragma unroll
            for (int mt = 0; mt < 4; mt++) {
                const __nv_bfloat16* pa = As + (size_t)((wm << 6) + (mt << 4) + g)*GP + kc;
                af[mt][0] = *(const uint32_t*)(pa);
                af[mt][1] = *(const uint32_t*)(pa + 8*GP);
                af[mt][2] = *(const uint32_t*)(pa + 8);
                af[mt][3] = *(const uint32_t*)(pa + 8*GP + 8);
            }
            #pragma unroll
            for (int nt = 0; nt < 4; nt++) {
                const __nv_bfloat16* pb = Bs + (size_t)((wn << 5) + (nt << 3) + g)*GP + kc;
                bf[nt][0] = *(const uint32_t*)(pb);
                bf[nt][1] = *(const uint32_t*)(pb + 8);
            }
            #pragma unroll
            for (int mt = 0; mt < 4; mt++)
                #pragma unroll
                for (int nt = 0; nt < 4; nt++) {
                    if (F16) mma_h (d[mt][nt], af[mt], bf[nt][0], bf[nt][1]);
                    else     mma_bf(d[mt][nt], af[mt], bf[nt][0], bf[nt][1]);
                }
        }
        __syncthreads();
        if (t + 1 < ns) {
            if (nseg == 0) {
                __nv_bfloat16* dA = SA[nq];
                __nv_bfloat16* dB = SB[nq];
                #pragma unroll
                for (int i = 0; i < 4; i++) {
                    int row = lrow + (i << 5);
                    *(uint4*)(dA + row*GP + (lch << 3)) = ra[i];
                    *(uint4*)(dB + row*GP + (lch << 3)) = rb[i];
                }
            } else if (nseg == 1) {
                __nv_bfloat16* dB = SB[nq ^ 1];
                #pragma unroll
                for (int i = 0; i < 4; i++) {
                    int row = lrow + (i << 5);
                    *(uint4*)(dB + row*GP + (lch << 3)) = rb[i];
                }
            } else {
                __nv_bfloat16* dA = SA[nq ^ 1];
                #pragma unroll
                for (int i = 0; i < 4; i++) {
                    int row = lrow + (i << 5);
                    *(uint4*)(dA + row*GP + (lch << 3)) = ra[i];
                }
            }
            __syncthreads();
        }
    }

    #pragma unroll
    for (int mt = 0; mt < 4; mt++) {
        #pragma unroll
        for (int nt = 0; nt < 4; nt++) {
            int n = n0 + (wn << 5) + (nt << 3) + (tig << 1);
            int m_lo = m0 + (wm << 6) + (mt << 4) + g;
            if (mode == 1) {
                const int w3 = n >> 10;
                __nv_bfloat16* tgt = (w3 == 0) ? g_q2 : (w3 == 1) ? g_k2 : g_v2;
                const float sc = (w3 == 0) ? 0.125f : 1.0f;
                float2 bb = *(const float2*)&g_bias[n];
                int h = (n & 1023) >> 6, d0 = n & 63;
                #pragma unroll
                for (int half = 0; half < 2; half++) {
                    int m = m_lo + half*8;
                    int b = m >> 11, s = m & 2047;
                    float x0 = (d[mt][nt][2*half]   + bb.x) * sc;
                    float x1 = (d[mt][nt][2*half+1] + bb.y) * sc;
                    uint32_t hh, ll;
                    split_pack_h(x0, x1, hh, ll);
                    size_t base = (((size_t)b*NHEAD + h)*S_LEN + s)*128 + d0;
                    *(uint32_t*)&tgt[base]      = hh;
                    *(uint32_t*)&tgt[base + 64] = ll;
                }
            } else if (mode == 2) {
                __nv_bfloat16* Cb = (__nv_bfloat16*)Cv + (long long)blockIdx.z * sC;
                *(uint32_t*)&Cb[(size_t)m_lo*ldc + n] =
                    pack_bf2(__float2bfloat16_rn(d[mt][nt][0]), __float2bfloat16_rn(d[mt][nt][1]));
                *(uint32_t*)&Cb[(size_t)(m_lo + 8)*ldc + n] =
                    pack_bf2(__float2bfloat16_rn(d[mt][nt][2]), __float2bfloat16_rn(d[mt][nt][3]));
            } else {
                float* C = (float*)Cv + (long long)blockIdx.z * sC;
                *(float2*)(C + (size_t)m_lo*ldc + n)       = make_float2(d[mt][nt][0], d[mt][nt][1]);
                *(float2*)(C + (size_t)(m_lo + 8)*ldc + n) = make_float2(d[mt][nt][2], d[mt][nt][3]);
            }
        }
    }
}

// ---------------- c2p table (q2 = fp16 split planes, q pre-scaled by 1/8) ----------------
__global__ void __launch_bounds__(256) c2p_kernel(const float* __restrict__ pt)
{
    const int bh = blockIdx.x;
    const __half* q2 = (const __half*)(g_q2 + (size_t)bh*S_LEN*128);
    __shared__ float part[256];
    __shared__ float qsum[64];
    const int tid = threadIdx.x;
    const int d = tid & 63, sg = tid >> 6;

    float acc = 0.f;
    for (int s = sg; s < S_LEN; s += 4) {
        const __half* row = q2 + (size_t)s*128;
        acc += __half2float(row[d]) + __half2float(row[64 + d]);
    }
    part[tid] = acc;
    __syncthreads();
    if (tid < 64) qsum[tid] = (part[tid] + part[tid+64] + part[tid+128] + part[tid+192]) * 8.0f;
    __syncthreads();

    const int u = (blockIdx.y << 8) + tid;
    float vsum = 0.f;
    #pragma unroll 16
    for (int dd = 0; dd < 64; dd++) vsum += qsum[dd] * pt[u*64 + dd];
    g_c2p[bh*NPOS + u] = vsum;
}

// ---------------- flash attention: fp16 HMMA, QK 1-term (qh*kh), PV 2-term ----------------
#define FGP 72
#define SQB_ELEMS (192*FGP)   // holds Q hi plane (128*FGP) and later the p2c band (191*FGP)
#define FLASH_SMEM_BYTES (SQB_ELEMS*2 + (64*FGP)*2 + (2*64*FGP)*2 + 1024*4)  // 59392 B

__global__ void __launch_bounds__(256, 2) flash_attn()
{
    const int bh = blockIdx.y;
    const int i0 = blockIdx.x << 7;
    const __nv_bfloat16* q2 = g_q2 + (size_t)bh*S_LEN*128;
    const __nv_bfloat16* k2 = g_k2 + (size_t)bh*S_LEN*128;
    const __nv_bfloat16* v2 = g_v2 + (size_t)bh*S_LEN*128;
    const float* c2p = g_c2p + bh*NPOS;
    const __nv_bfloat16* p2cb = g_p2cb + (size_t)bh*NPOS*S_LEN;

    extern __shared__ __nv_bfloat16 smb[];
    __nv_bfloat16* sq   = smb;                  // Q hi plane; reused as p2c band
    __nv_bfloat16* stgb = smb;                  // [191][72] bf16 (alias)
    __nv_bfloat16* sk   = smb + SQB_ELEMS;      // K hi plane only
    __nv_bfloat16* sv   = sk + 64*FGP;          // V: 2 planes
    float* c2ps = (float*)(sv + 2*64*FGP);

    const uint32_t sq_u = smem_u32(sq);
    const uint32_t sk_u = smem_u32(sk);
    const uint32_t sv_u = smem_u32(sv);

    const int tid = threadIdx.x;
    const int wid = tid >> 5;
    const int lane = tid & 31;
    const int g = lane >> 2, tig = lane & 3;
    const int lro = ((lane >> 3) & 1) << 3;
    const int lr8 = lane & 7;
    const int lco = (lane >> 4) << 3;

    // load Q hi plane: row = tid>>1, 32-elem part = tid&1 (4 uint4 each)
    {
        int row = tid >> 1, part = tid & 1;
        const uint4* s4 = (const uint4*)(q2 + (size_t)(i0 + row)*128 + part*32);
        uint4* d4 = (uint4*)(sq + row*FGP + part*32);
        d4[0] = s4[0]; d4[1] = s4[1]; d4[2] = s4[2]; d4[3] = s4[3];
    }
    for (int u = tid; u < NPOS; u += 256) c2ps[u] = c2p[u];
    __syncthreads();

    // preload Q fragments (hi plane only)
    uint32_t qf[4][4];
    #pragma unroll
    for (int kc = 0; kc < 4; kc++)
        ldsm_x4(qf[kc], sq_u + (((wid << 4) + lro + lr8)*FGP + lco + kc*16)*2);

    float o[8][4];
    #pragma unroll
    for (int nt = 0; nt < 8; nt++)
        #pragma unroll
        for (int e = 0; e < 4; e++) o[nt][e] = 0.f;
    float mx[2] = {-1e30f, -1e30f}, lsum[2] = {0.f, 0.f};

    const int rl0 = (wid << 4) + g;

    for (int j0 = 0; j0 < S_LEN; j0 += 64) {
        __syncthreads();
        for (int idx = tid; idx < 512; idx += 256) {
            int row = idx >> 3, ch = (idx & 7) << 3;
            *(uint4*)(sk + row*FGP + ch) = *(const uint4*)(k2 + (size_t)(j0 + row)*128 + ch);
        }
        for (int idx = tid; idx < 1024; idx += 256) {
            int p = idx >> 9, rem = idx & 511;
            int row = rem >> 3, ch = (rem & 7) << 3;
            *(uint4*)(sv + (p*64 + row)*FGP + ch) =
                *(const uint4*)(v2 + (size_t)(j0 + row)*128 + p*64 + ch);
        }
        const int u_lo = 2369 - i0 - j0;
        for (int idx = tid; idx < 191*8; idx += 256) {
            int su = idx >> 3, c8 = (idx & 7) << 3;
            int u = min(max(u_lo + su, 0), NPOS - 1);
            *(uint4*)&stgb[su*FGP + c8] = *(const uint4*)&p2cb[(size_t)u*S_LEN + j0 + c8];
        }
        __syncthreads();

        // ---- S = qh @ kh^T (fp16) ----
        float s[8][4];
        #pragma unroll
        for (int nt = 0; nt < 8; nt++)
            #pragma unroll
            for (int e = 0; e < 4; e++) s[nt][e] = 0.f;

        #pragma unroll
        for (int kc = 0; kc < 4; kc++) {
            #pragma unroll
            for (int t = 0; t < 4; t++) {
                uint32_t kf[4];
                ldsm_x4(kf, sk_u + (((t << 4) + lro + lr8)*FGP + lco + kc*16)*2);
                mma_h(s[2*t],   qf[kc], kf[0], kf[2]);
                mma_h(s[2*t+1], qf[kc], kf[1], kf[3]);
            }
        }

        // ---- bias ----
        #pragma unroll
        for (int rr = 0; rr < 2; rr++) {
            int rl = rl0 + rr*8;
            int r  = i0 + rl;
            #pragma unroll
            for (int nt = 0; nt < 8; nt++)
                #pragma unroll
                for (int e = 0; e < 2; e++) {
                    int cl = (nt << 3) + (tig << 1) + e;
                    int ic = min(max(r - (j0 + cl) + 512, 0), NPOS - 1);
                    s[nt][rr*2 + e] += c2ps[ic] + __bfloat162float(stgb[(190 - rl - cl)*FGP + cl]);
                }
        }

        // ---- online softmax ----
        float fac[2];
        #pragma unroll
        for (int rr = 0; rr < 2; rr++) {
            float rm = -1e30f;
            #pragma unroll
            for (int nt = 0; nt < 8; nt++)
                rm = fmaxf(rm, fmaxf(s[nt][rr*2], s[nt][rr*2+1]));
            rm = fmaxf(rm, __shfl_xor_sync(0xffffffffu, rm, 1));
            rm = fmaxf(rm, __shfl_xor_sync(0xffffffffu, rm, 2));
            float mn = fmaxf(mx[rr], rm);
            fac[rr] = __expf(mx[rr] - mn);
            mx[rr] = mn;
            float rs = 0.f;
            #pragma unroll
            for (int nt = 0; nt < 8; nt++) {
                s[nt][rr*2]   = __expf(s[nt][rr*2]   - mn);
                s[nt][rr*2+1] = __expf(s[nt][rr*2+1] - mn);
                rs += s[nt][rr*2] + s[nt][rr*2+1];
            }
            rs += __shfl_xor_sync(0xffffffffu, rs, 1);
            rs += __shfl_xor_sync(0xffffffffu, rs, 2);
            lsum[rr] = lsum[rr]*fac[rr] + rs;
        }
        #pragma unroll
        for (int nt = 0; nt < 8; nt++) {
            o[nt][0] *= fac[0]; o[nt][1] *= fac[0];
            o[nt][2] *= fac[1]; o[nt][3] *= fac[1];
        }

        // ---- O += P @ V: P single fp16, V fp16 split: p*vh + p*vl ----
        #pragma unroll
        for (int kc = 0; kc < 4; kc++) {
            uint32_t ph[4];
            ph[0] = pack_h2(s[2*kc][0],   s[2*kc][1]);
            ph[1] = pack_h2(s[2*kc][2],   s[2*kc][3]);
            ph[2] = pack_h2(s[2*kc+1][0], s[2*kc+1][1]);
            ph[3] = pack_h2(s[2*kc+1][2], s[2*kc+1][3]);
            #pragma unroll
            for (int nd = 0; nd < 4; nd++) {
                uint32_t vf[4], vl[4];
                ldsm_x4_t(vf, sv_u + (((kc << 4) + lro + lr8)*FGP + (nd << 4) + lco)*2);
                ldsm_x4_t(vl, sv_u + ((64 + (kc << 4) + lro + lr8)*FGP + (nd << 4) + lco)*2);
                mma_h(o[2*nd],   ph, vf[0], vf[1]);
                mma_h(o[2*nd+1], ph, vf[2], vf[3]);
                mma_h(o[2*nd],   ph, vl[0], vl[1]);
                mma_h(o[2*nd+1], ph, vl[2], vl[3]);
            }
        }
    }

    // ---- epilogue: bf16 split planes -> g_ao2 ----
    const int b = bh >> 4, h = bh & 15;
    #pragma unroll
    for (int rr = 0; rr < 2; rr++) {
        int m = b*S_LEN + i0 + rl0 + rr*8;
        float inv = 1.0f / lsum[rr];
        __nv_bfloat16* dst = g_ao2 + (size_t)m*2048 + h*64;
        #pragma unroll
        for (int nt = 0; nt < 8; nt++) {
            int d0 = (nt << 3) + (tig << 1);
            uint32_t hh, ll;
            split_pack(o[nt][rr*2]*inv, o[nt][rr*2+1]*inv, hh, ll);
            *(uint32_t*)&dst[d0]        = hh;
            *(uint32_t*)&dst[1024 + d0] = ll;
        }
    }
}

// ---------------- launch ----------------
extern "C" void kernel_launch(void* const* d_in, const int* in_sizes, int n_in,
                              void* d_out, int out_size)
{
    const float* hidden = (const float*)d_in[0];
    const float* Wq = (const float*)d_in[1];
    const float* bq = (const float*)d_in[2];
    const float* Wk = (const float*)d_in[3];
    const float* bk = (const float*)d_in[4];
    const float* Wv = (const float*)d_in[5];
    const float* bv = (const float*)d_in[6];
    const float* Wc = (const float*)d_in[7];
    const float* pt = (const float*)d_in[8];
    float* out = (float*)d_out;

    __nv_bfloat16 *px2, *pw2, *pwc2, *ppt2, *pk2, *pao2, *pp2cb;
    cudaGetSymbolAddress((void**)&pp2cb, g_p2cb);
    cudaGetSymbolAddress((void**)&px2,  g_x2);
    cudaGetSymbolAddress((void**)&pw2,  g_w2);
    cudaGetSymbolAddress((void**)&pwc2, g_wc2);
    cudaGetSymbolAddress((void**)&ppt2, g_pt2);
    cudaGetSymbolAddress((void**)&pk2,  g_k2);
    cudaGetSymbolAddress((void**)&pao2, g_ao2);

    const int gemm_smem = 4 * STAGE * (int)sizeof(__nv_bfloat16);
    static int once = 0;
    if (!once) {
        cudaFuncSetAttribute(flash_attn, cudaFuncAttributeMaxDynamicSharedMemorySize, FLASH_SMEM_BYTES);
        cudaFuncSetAttribute(hmma_gemm<false>, cudaFuncAttributeMaxDynamicSharedMemorySize, gemm_smem);
        cudaFuncSetAttribute(hmma_gemm<true>,  cudaFuncAttributeMaxDynamicSharedMemorySize, gemm_smem);
        once = 1;
    }

    cvt_split<<<4096, 256>>>(hidden, px2, 10, (long long)4096*1024/4, 0);
    cvt_split<<<1024, 256>>>(Wq, pw2,                     10, (long long)1024*1024/4, 0);
    cvt_split<<<1024, 256>>>(Wk, pw2 + (size_t)1024*2048, 10, (long long)1024*1024/4, 0);
    cvt_split<<<1024, 256>>>(Wv, pw2 + (size_t)2048*2048, 10, (long long)1024*1024/4, 0);
    cvt_split<<<1024, 256>>>(Wc, pwc2,                    10, (long long)1024*1024/4, 0);
    cvt_split<<<64,   256>>>(pt, ppt2,                     6, (long long)1024*64/4,   1);
    bias_concat<<<12, 256>>>(bq, bk, bv);

    // QKV (bf16 3-term) -> fp16 split planes
    hmma_gemm<false><<<dim3(24, 32, 1), 256, gemm_smem>>>(
        px2, 2048, 0, pw2, 2048, 0, nullptr, 0, 0, 1024, 1);

    c2p_kernel<<<dim3(BH, 4), 256>>>(pt);

    // P2C (fp16 3-term) -> bf16
    hmma_gemm<true><<<dim3(16, 8, BH), 256, gemm_smem>>>(
        ppt2, 128, 0, pk2, 128, (long long)S_LEN*128,
        pp2cb, S_LEN, (long long)NPOS*S_LEN, 64, 2);

    flash_attn<<<dim3(S_LEN/128, BH), 256, FLASH_SMEM_BYTES>>>();

    // c_proj (bf16 3-term)
    hmma_gemm<false><<<dim3(8, 32, 1), 256, gemm_smem>>>(
        pao2, 2048, 0, pwc2, 2048, 0, out, DMODEL, 0, 1024, 0);
}

// round 17
// speedup vs baseline: 1.5169x; 1.0936x over previous
#include <cuda_runtime.h>
#include <cuda_bf16.h>
#include <cuda_fp16.h>
#include <math.h>
#include <stdint.h>

#define S_LEN  2048
#define NHEAD  16
#define DHEAD  64
#define BATCH  2
#define DMODEL 1024
#define BH     (BATCH*NHEAD)
#define NPOS   1024

// ---------------- static scratch ----------------
__device__ float g_c2p[BH*NPOS];
__device__ float g_bias[3072];
__device__ __align__(16) __nv_bfloat16 g_p2cb[(size_t)BH*NPOS*S_LEN];  // bf16 [bh][u][j]

__device__ __align__(16) __nv_bfloat16 g_x2 [(size_t)4096*2048];   // bf16 split
__device__ __align__(16) __nv_bfloat16 g_w2 [(size_t)3072*2048];   // bf16 split
__device__ __align__(16) __nv_bfloat16 g_wc2[(size_t)1024*2048];   // bf16 split
__device__ __align__(16) __nv_bfloat16 g_pt2[(size_t)1024*128];    // fp16 split (bits)
__device__ __align__(16) __nv_bfloat16 g_ao2[(size_t)4096*2048];   // bf16 split
// q/k/v fp16 split planes [bh][s][hi 64 | lo 64]; q pre-scaled by 0.125
__device__ __align__(16) __nv_bfloat16 g_q2 [(size_t)BH*S_LEN*128];
__device__ __align__(16) __nv_bfloat16 g_k2 [(size_t)BH*S_LEN*128];
__device__ __align__(16) __nv_bfloat16 g_v2 [(size_t)BH*S_LEN*128];

// ---------------- helpers ----------------
__device__ __forceinline__ void mma_bf(float* d, const uint32_t* a, uint32_t b0, uint32_t b1) {
    asm volatile(
        "mma.sync.aligned.m16n8k16.row.col.f32.bf16.bf16.f32 "
        "{%0,%1,%2,%3}, {%4,%5,%6,%7}, {%8,%9}, {%0,%1,%2,%3};"
        : "+f"(d[0]), "+f"(d[1]), "+f"(d[2]), "+f"(d[3])
        : "r"(a[0]), "r"(a[1]), "r"(a[2]), "r"(a[3]), "r"(b0), "r"(b1));
}
__device__ __forceinline__ void mma_h(float* d, const uint32_t* a, uint32_t b0, uint32_t b1) {
    asm volatile(
        "mma.sync.aligned.m16n8k16.row.col.f32.f16.f16.f32 "
        "{%0,%1,%2,%3}, {%4,%5,%6,%7}, {%8,%9}, {%0,%1,%2,%3};"
        : "+f"(d[0]), "+f"(d[1]), "+f"(d[2]), "+f"(d[3])
        : "r"(a[0]), "r"(a[1]), "r"(a[2]), "r"(a[3]), "r"(b0), "r"(b1));
}
__device__ __forceinline__ void ldsm_x4(uint32_t* r, uint32_t a) {
    asm volatile("ldmatrix.sync.aligned.m8n8.x4.shared.b16 {%0,%1,%2,%3}, [%4];"
                 : "=r"(r[0]), "=r"(r[1]), "=r"(r[2]), "=r"(r[3]) : "r"(a));
}
__device__ __forceinline__ void ldsm_x4_t(uint32_t* r, uint32_t a) {
    asm volatile("ldmatrix.sync.aligned.m8n8.x4.trans.shared.b16 {%0,%1,%2,%3}, [%4];"
                 : "=r"(r[0]), "=r"(r[1]), "=r"(r[2]), "=r"(r[3]) : "r"(a));
}
__device__ __forceinline__ uint32_t smem_u32(const void* p) {
    uint32_t a;
    asm("{ .reg .u64 t; cvta.to.shared.u64 t, %1; cvt.u32.u64 %0, t; }" : "=r"(a) : "l"(p));
    return a;
}
__device__ __forceinline__ uint32_t pack_bf2(__nv_bfloat16 a, __nv_bfloat16 b) {
    return (uint32_t)__bfloat16_as_ushort(a) | ((uint32_t)__bfloat16_as_ushort(b) << 16);
}
__device__ __forceinline__ void split_pack(float x0, float x1, uint32_t& h, uint32_t& l) {
    __nv_bfloat16 h0 = __float2bfloat16_rn(x0), h1 = __float2bfloat16_rn(x1);
    h = pack_bf2(h0, h1);
    l = pack_bf2(__float2bfloat16_rn(x0 - __bfloat162float(h0)),
                 __float2bfloat16_rn(x1 - __bfloat162float(h1)));
}
__device__ __forceinline__ uint32_t pack_h2(float a, float b) {
    __half2 h = __floats2half2_rn(a, b);
    return *(uint32_t*)&h;
}
__device__ __forceinline__ void split_pack_h(float x0, float x1, uint32_t& h, uint32_t& l) {
    __half h0 = __float2half_rn(x0), h1 = __float2half_rn(x1);
    h = (uint32_t)__half_as_ushort(h0) | ((uint32_t)__half_as_ushort(h1) << 16);
    l = (uint32_t)__half_as_ushort(__float2half_rn(x0 - __half2float(h0))) |
        ((uint32_t)__half_as_ushort(__float2half_rn(x1 - __half2float(h1))) << 16);
}

// ---------------- split conversion (bf16 or fp16) ----------------
__global__ void __launch_bounds__(256) cvt_split(
    const float* __restrict__ src, __nv_bfloat16* __restrict__ dst,
    int kshift, long long n4, int use_f16)
{
    long long i = (long long)blockIdx.x * 256 + threadIdx.x;
    if (i >= n4) return;
    long long e = i << 2;
    const int K = 1 << kshift;
    long long row = e >> kshift;
    int col = (int)(e & (K - 1));
    float4 v = *(const float4*)(src + e);
    uint32_t h01, l01, h23, l23;
    if (use_f16) {
        split_pack_h(v.x, v.y, h01, l01);
        split_pack_h(v.z, v.w, h23, l23);
    } else {
        split_pack(v.x, v.y, h01, l01);
        split_pack(v.z, v.w, h23, l23);
    }
    __nv_bfloat16* drow = dst + (row << (kshift + 1));
    *(uint2*)(drow + col)     = make_uint2(h01, h23);
    *(uint2*)(drow + K + col) = make_uint2(l01, l23);
}

__global__ void bias_concat(const float* __restrict__ bq, const float* __restrict__ bk,
                            const float* __restrict__ bv)
{
    int i = blockIdx.x * 256 + threadIdx.x;
    if (i >= 3072) return;
    g_bias[i] = (i < 1024) ? bq[i] : (i < 2048) ? bk[i - 1024] : bv[i - 2048];
}

// ---------------- HMMA GEMM (3-term split, r-major segment schedule) ----------------
// F16: operands are fp16 splits; else bf16 splits.
// mode 0: fp32 C.  mode 1: qkv scatter+bias -> FP16 split planes.  mode 2: bf16 C.
#define GP 72
#define STAGE (128*GP)
template<bool F16>
__global__ void __launch_bounds__(256, 2) hmma_gemm(
    const __nv_bfloat16* __restrict__ A2, int lda2, long long sA,
    const __nv_bfloat16* __restrict__ B2, int ldb2, long long sB,
    void* __restrict__ Cv, int ldc, long long sC, int K, int mode)
{
    extern __shared__ __nv_bfloat16 sb[];
    const int tid  = threadIdx.x;
    const int wid  = tid >> 5;
    const int lane = tid & 31;
    const int g    = lane >> 2;
    const int tig  = lane & 3;
    const int wm   = wid >> 2;
    const int wn   = wid & 3;

    const int n0 = blockIdx.x << 7;
    const int m0 = blockIdx.y << 7;

    A2 += (long long)blockIdx.z * sA + (size_t)m0 * lda2;
    B2 += (long long)blockIdx.z * sB + (size_t)n0 * ldb2;

    const int ns = 3 * (K >> 6);
    const int lrow = tid >> 3;
    const int lch  = tid & 7;

    __nv_bfloat16* SA[2] = { sb,             sb + STAGE };
    __nv_bfloat16* SB[2] = { sb + 2*STAGE,   sb + 3*STAGE };

    float d[4][4][4];
    #pragma unroll
    for (int a = 0; a < 4; a++)
        #pragma unroll
        for (int b = 0; b < 4; b++)
            #pragma unroll
            for (int c = 0; c < 4; c++) d[a][b][c] = 0.f;

    #pragma unroll
    for (int i = 0; i < 4; i++) {
        int row = lrow + (i << 5);
        *(uint4*)(SA[0] + row*GP + (lch << 3)) = *(const uint4*)(A2 + (size_t)row*lda2 + (lch << 3));
        *(uint4*)(SB[0] + row*GP + (lch << 3)) = *(const uint4*)(B2 + (size_t)row*ldb2 + (lch << 3));
    }
    __syncthreads();

    for (int t = 0; t < ns; t++) {
        const int r   = t / 3;
        const int seg = t - 3*r;
        const int q   = r & 1;

        uint4 ra[4], rb[4];
        int nseg = -1, nq = 0;
        if (t + 1 < ns) {
            int t1 = t + 1;
            int r1 = t1 / 3; nseg = t1 - 3*r1; nq = r1 & 1;
            if (nseg == 0) {
                const __nv_bfloat16* ga = A2 + (r1 << 6);
                const __nv_bfloat16* gb = B2 + (r1 << 6);
                #pragma unroll
                for (int i = 0; i < 4; i++) {
                    int row = lrow + (i << 5);
                    ra[i] = *(const uint4*)(ga + (size_t)row*lda2 + (lch << 3));
                    rb[i] = *(const uint4*)(gb + (size_t)row*ldb2 + (lch << 3));
                }
            } else if (nseg == 1) {
                const __nv_bfloat16* gb = B2 + K + (r1 << 6);
                #pragma unroll
                for (int i = 0; i < 4; i++) {
                    int row = lrow + (i << 5);
                    rb[i] = *(const uint4*)(gb + (size_t)row*ldb2 + (lch << 3));
                }
            } else {
                const __nv_bfloat16* ga = A2 + K + (r1 << 6);
                #pragma unroll
                for (int i = 0; i < 4; i++) {
                    int row = lrow + (i << 5);
                    ra[i] = *(const uint4*)(ga + (size_t)row*lda2 + (lch << 3));
                }
            }
        }

        const __nv_bfloat16* As = SA[(seg == 2) ? (q ^ 1) : q];
        const __nv_bfloat16* Bs = SB[(seg == 1) ? (q ^ 1) : q];
        #pragma unroll
        for (int kk = 0; kk < 4; kk++) {
            const int kc = (kk << 4) + (tig << 1);
            uint32_t af[4][4], bf[4][2];
            #pragma unroll
            for (int mt = 0; mt < 4; mt++) {
                const __nv_bfloat16* pa = As + (size_t)((wm << 6) + (mt << 4) + g)*GP + kc;
                af[mt][0] = *(const uint32_t*)(pa);
                af[mt][1] = *(const uint32_t*)(pa + 8*GP);
                af[mt][2] = *(const uint32_t*)(pa + 8);
                af[mt][3] = *(const uint32_t*)(pa + 8*GP + 8);
            }
            #pragma unroll
            for (int nt = 0; nt < 4; nt++) {
                const __nv_bfloat16* pb = Bs + (size_t)((wn << 5) + (nt << 3) + g)*GP + kc;
                bf[nt][0] = *(const uint32_t*)(pb);
                bf[nt][1] = *(const uint32_t*)(pb + 8);
            }
            #pragma unroll
            for (int mt = 0; mt < 4; mt++)
                #pragma unroll
                for (int nt = 0; nt < 4; nt++) {
                    if (F16) mma_h (d[mt][nt], af[mt], bf[nt][0], bf[nt][1]);
                    else     mma_bf(d[mt][nt], af[mt], bf[nt][0], bf[nt][1]);
                }
        }
        __syncthreads();
        if (t + 1 < ns) {
            if (nseg == 0) {
                __nv_bfloat16* dA = SA[nq];
                __nv_bfloat16* dB = SB[nq];
                #pragma unroll
                for (int i = 0; i < 4; i++) {
                    int row = lrow + (i << 5);
                    *(uint4*)(dA + row*GP + (lch << 3)) = ra[i];
                    *(uint4*)(dB + row*GP + (lch << 3)) = rb[i];
                }
            } else if (nseg == 1) {
                __nv_bfloat16* dB = SB[nq ^ 1];
                #pragma unroll
                for (int i = 0; i < 4; i++) {
                    int row = lrow + (i << 5);
                    *(uint4*)(dB + row*GP + (lch << 3)) = rb[i];
                }
            } else {
                __nv_bfloat16* dA = SA[nq ^ 1];
                #pragma unroll
                for (int i = 0; i < 4; i++) {
                    int row = lrow + (i << 5);
                    *(uint4*)(dA + row*GP + (lch << 3)) = ra[i];
                }
            }
            __syncthreads();
        }
    }

    #pragma unroll
    for (int mt = 0; mt < 4; mt++) {
        #pragma unroll
        for (int nt = 0; nt < 4; nt++) {
            int n = n0 + (wn << 5) + (nt << 3) + (tig << 1);
            int m_lo = m0 + (wm << 6) + (mt << 4) + g;
            if (mode == 1) {
                const int w3 = n >> 10;
                __nv_bfloat16* tgt = (w3 == 0) ? g_q2 : (w3 == 1) ? g_k2 : g_v2;
                const float sc = (w3 == 0) ? 0.125f : 1.0f;
                float2 bb = *(const float2*)&g_bias[n];
                int h = (n & 1023) >> 6, d0 = n & 63;
                #pragma unroll
                for (int half = 0; half < 2; half++) {
                    int m = m_lo + half*8;
                    int b = m >> 11, s = m & 2047;
                    float x0 = (d[mt][nt][2*half]   + bb.x) * sc;
                    float x1 = (d[mt][nt][2*half+1] + bb.y) * sc;
                    uint32_t hh, ll;
                    split_pack_h(x0, x1, hh, ll);
                    size_t base = (((size_t)b*NHEAD + h)*S_LEN + s)*128 + d0;
                    *(uint32_t*)&tgt[base]      = hh;
                    *(uint32_t*)&tgt[base + 64] = ll;
                }
            } else if (mode == 2) {
                __nv_bfloat16* Cb = (__nv_bfloat16*)Cv + (long long)blockIdx.z * sC;
                *(uint32_t*)&Cb[(size_t)m_lo*ldc + n] =
                    pack_bf2(__float2bfloat16_rn(d[mt][nt][0]), __float2bfloat16_rn(d[mt][nt][1]));
                *(uint32_t*)&Cb[(size_t)(m_lo + 8)*ldc + n] =
                    pack_bf2(__float2bfloat16_rn(d[mt][nt][2]), __float2bfloat16_rn(d[mt][nt][3]));
            } else {
                float* C = (float*)Cv + (long long)blockIdx.z * sC;
                *(float2*)(C + (size_t)m_lo*ldc + n)       = make_float2(d[mt][nt][0], d[mt][nt][1]);
                *(float2*)(C + (size_t)(m_lo + 8)*ldc + n) = make_float2(d[mt][nt][2], d[mt][nt][3]);
            }
        }
    }
}

// ---------------- c2p table (q2 = fp16 split planes, q pre-scaled by 1/8) ----------------
__global__ void __launch_bounds__(256) c2p_kernel(const float* __restrict__ pt)
{
    const int bh = blockIdx.x;
    const __half* q2 = (const __half*)(g_q2 + (size_t)bh*S_LEN*128);
    __shared__ float part[256];
    __shared__ float qsum[64];
    const int tid = threadIdx.x;
    const int d = tid & 63, sg = tid >> 6;

    float acc = 0.f;
    for (int s = sg; s < S_LEN; s += 4) {
        const __half* row = q2 + (size_t)s*128;
        acc += __half2float(row[d]) + __half2float(row[64 + d]);
    }
    part[tid] = acc;
    __syncthreads();
    if (tid < 64) qsum[tid] = (part[tid] + part[tid+64] + part[tid+128] + part[tid+192]) * 8.0f;
    __syncthreads();

    const int u = (blockIdx.y << 8) + tid;
    float vsum = 0.f;
    #pragma unroll 16
    for (int dd = 0; dd < 64; dd++) vsum += qsum[dd] * pt[u*64 + dd];
    g_c2p[bh*NPOS + u] = vsum;
}

// ---------------- flash attention: fp16 HMMA, QK 1-term, PV 1-term ----------------
#define FGP 72
#define SQB_ELEMS (192*FGP)   // holds Q hi plane (128*FGP) and later the p2c band (191*FGP)
#define FLASH_SMEM_BYTES (SQB_ELEMS*2 + (64*FGP)*2 + (64*FGP)*2 + 1024*4)  // 50176 B

__global__ void __launch_bounds__(256, 2) flash_attn()
{
    const int bh = blockIdx.y;
    const int i0 = blockIdx.x << 7;
    const __nv_bfloat16* q2 = g_q2 + (size_t)bh*S_LEN*128;
    const __nv_bfloat16* k2 = g_k2 + (size_t)bh*S_LEN*128;
    const __nv_bfloat16* v2 = g_v2 + (size_t)bh*S_LEN*128;
    const float* c2p = g_c2p + bh*NPOS;
    const __nv_bfloat16* p2cb = g_p2cb + (size_t)bh*NPOS*S_LEN;

    extern __shared__ __nv_bfloat16 smb[];
    __nv_bfloat16* sq   = smb;                  // Q hi plane; reused as p2c band
    __nv_bfloat16* stgb = smb;                  // [191][72] bf16 (alias)
    __nv_bfloat16* sk   = smb + SQB_ELEMS;      // K hi plane
    __nv_bfloat16* sv   = sk + 64*FGP;          // V hi plane
    float* c2ps = (float*)(sv + 64*FGP);

    const uint32_t sq_u = smem_u32(sq);
    const uint32_t sk_u = smem_u32(sk);
    const uint32_t sv_u = smem_u32(sv);

    const int tid = threadIdx.x;
    const int wid = tid >> 5;
    const int lane = tid & 31;
    const int g = lane >> 2, tig = lane & 3;
    const int lro = ((lane >> 3) & 1) << 3;
    const int lr8 = lane & 7;
    const int lco = (lane >> 4) << 3;

    // load Q hi plane
    {
        int row = tid >> 1, part = tid & 1;
        const uint4* s4 = (const uint4*)(q2 + (size_t)(i0 + row)*128 + part*32);
        uint4* d4 = (uint4*)(sq + row*FGP + part*32);
        d4[0] = s4[0]; d4[1] = s4[1]; d4[2] = s4[2]; d4[3] = s4[3];
    }
    for (int u = tid; u < NPOS; u += 256) c2ps[u] = c2p[u];
    __syncthreads();

    // preload Q fragments (hi plane only)
    uint32_t qf[4][4];
    #pragma unroll
    for (int kc = 0; kc < 4; kc++)
        ldsm_x4(qf[kc], sq_u + (((wid << 4) + lro + lr8)*FGP + lco + kc*16)*2);

    float o[8][4];
    #pragma unroll
    for (int nt = 0; nt < 8; nt++)
        #pragma unroll
        for (int e = 0; e < 4; e++) o[nt][e] = 0.f;
    float mx[2] = {-1e30f, -1e30f}, lsum[2] = {0.f, 0.f};

    const int rl0 = (wid << 4) + g;

    for (int j0 = 0; j0 < S_LEN; j0 += 64) {
        __syncthreads();
        // K hi + V hi planes: 64 rows x 8 uint4 each
        for (int idx = tid; idx < 512; idx += 256) {
            int row = idx >> 3, ch = (idx & 7) << 3;
            *(uint4*)(sk + row*FGP + ch) = *(const uint4*)(k2 + (size_t)(j0 + row)*128 + ch);
            *(uint4*)(sv + row*FGP + ch) = *(const uint4*)(v2 + (size_t)(j0 + row)*128 + ch);
        }
        // p2c band (bf16)
        const int u_lo = 2369 - i0 - j0;
        for (int idx = tid; idx < 191*8; idx += 256) {
            int su = idx >> 3, c8 = (idx & 7) << 3;
            int u = min(max(u_lo + su, 0), NPOS - 1);
            *(uint4*)&stgb[su*FGP + c8] = *(const uint4*)&p2cb[(size_t)u*S_LEN + j0 + c8];
        }
        __syncthreads();

        // ---- S = qh @ kh^T (fp16) ----
        float s[8][4];
        #pragma unroll
        for (int nt = 0; nt < 8; nt++)
            #pragma unroll
            for (int e = 0; e < 4; e++) s[nt][e] = 0.f;

        #pragma unroll
        for (int kc = 0; kc < 4; kc++) {
            #pragma unroll
            for (int t = 0; t < 4; t++) {
                uint32_t kf[4];
                ldsm_x4(kf, sk_u + (((t << 4) + lro + lr8)*FGP + lco + kc*16)*2);
                mma_h(s[2*t],   qf[kc], kf[0], kf[2]);
                mma_h(s[2*t+1], qf[kc], kf[1], kf[3]);
            }
        }

        // ---- bias ----
        #pragma unroll
        for (int rr = 0; rr < 2; rr++) {
            int rl = rl0 + rr*8;
            int r  = i0 + rl;
            #pragma unroll
            for (int nt = 0; nt < 8; nt++)
                #pragma unroll
                for (int e = 0; e < 2; e++) {
                    int cl = (nt << 3) + (tig << 1) + e;
                    int ic = min(max(r - (j0 + cl) + 512, 0), NPOS - 1);
                    s[nt][rr*2 + e] += c2ps[ic] + __bfloat162float(stgb[(190 - rl - cl)*FGP + cl]);
                }
        }

        // ---- online softmax ----
        float fac[2];
        #pragma unroll
        for (int rr = 0; rr < 2; rr++) {
            float rm = -1e30f;
            #pragma unroll
            for (int nt = 0; nt < 8; nt++)
                rm = fmaxf(rm, fmaxf(s[nt][rr*2], s[nt][rr*2+1]));
            rm = fmaxf(rm, __shfl_xor_sync(0xffffffffu, rm, 1));
            rm = fmaxf(rm, __shfl_xor_sync(0xffffffffu, rm, 2));
            float mn = fmaxf(mx[rr], rm);
            fac[rr] = __expf(mx[rr] - mn);
            mx[rr] = mn;
            float rs = 0.f;
            #pragma unroll
            for (int nt = 0; nt < 8; nt++) {
                s[nt][rr*2]   = __expf(s[nt][rr*2]   - mn);
                s[nt][rr*2+1] = __expf(s[nt][rr*2+1] - mn);
                rs += s[nt][rr*2] + s[nt][rr*2+1];
            }
            rs += __shfl_xor_sync(0xffffffffu, rs, 1);
            rs += __shfl_xor_sync(0xffffffffu, rs, 2);
            lsum[rr] = lsum[rr]*fac[rr] + rs;
        }
        #pragma unroll
        for (int nt = 0; nt < 8; nt++) {
            o[nt][0] *= fac[0]; o[nt][1] *= fac[0];
            o[nt][2] *= fac[1]; o[nt][3] *= fac[1];
        }

        // ---- O += P @ V: P single fp16, V hi only ----
        #pragma unroll
        for (int kc = 0; kc < 4; kc++) {
            uint32_t ph[4];
            ph[0] = pack_h2(s[2*kc][0],   s[2*kc][1]);
            ph[1] = pack_h2(s[2*kc][2],   s[2*kc][3]);
            ph[2] = pack_h2(s[2*kc+1][0], s[2*kc+1][1]);
            ph[3] = pack_h2(s[2*kc+1][2], s[2*kc+1][3]);
            #pragma unroll
            for (int nd = 0; nd < 4; nd++) {
                uint32_t vf[4];
                ldsm_x4_t(vf, sv_u + (((kc << 4) + lro + lr8)*FGP + (nd << 4) + lco)*2);
                mma_h(o[2*nd],   ph, vf[0], vf[1]);
                mma_h(o[2*nd+1], ph, vf[2], vf[3]);
            }
        }
    }

    // ---- epilogue: bf16 split planes -> g_ao2 ----
    const int b = bh >> 4, h = bh & 15;
    #pragma unroll
    for (int rr = 0; rr < 2; rr++) {
        int m = b*S_LEN + i0 + rl0 + rr*8;
        float inv = 1.0f / lsum[rr];
        __nv_bfloat16* dst = g_ao2 + (size_t)m*2048 + h*64;
        #pragma unroll
        for (int nt = 0; nt < 8; nt++) {
            int d0 = (nt << 3) + (tig << 1);
            uint32_t hh, ll;
            split_pack(o[nt][rr*2]*inv, o[nt][rr*2+1]*inv, hh, ll);
            *(uint32_t*)&dst[d0]        = hh;
            *(uint32_t*)&dst[1024 + d0] = ll;
        }
    }
}

// ---------------- launch ----------------
extern "C" void kernel_launch(void* const* d_in, const int* in_sizes, int n_in,
                              void* d_out, int out_size)
{
    const float* hidden = (const float*)d_in[0];
    const float* Wq = (const float*)d_in[1];
    const float* bq = (const float*)d_in[2];
    const float* Wk = (const float*)d_in[3];
    const float* bk = (const float*)d_in[4];
    const float* Wv = (const float*)d_in[5];
    const float* bv = (const float*)d_in[6];
    const float* Wc = (const float*)d_in[7];
    const float* pt = (const float*)d_in[8];
    float* out = (float*)d_out;

    __nv_bfloat16 *px2, *pw2, *pwc2, *ppt2, *pk2, *pao2, *pp2cb;
    cudaGetSymbolAddress((void**)&pp2cb, g_p2cb);
    cudaGetSymbolAddress((void**)&px2,  g_x2);
    cudaGetSymbolAddress((void**)&pw2,  g_w2);
    cudaGetSymbolAddress((void**)&pwc2, g_wc2);
    cudaGetSymbolAddress((void**)&ppt2, g_pt2);
    cudaGetSymbolAddress((void**)&pk2,  g_k2);
    cudaGetSymbolAddress((void**)&pao2, g_ao2);

    const int gemm_smem = 4 * STAGE * (int)sizeof(__nv_bfloat16);
    static int once = 0;
    if (!once) {
        cudaFuncSetAttribute(flash_attn, cudaFuncAttributeMaxDynamicSharedMemorySize, FLASH_SMEM_BYTES);
        cudaFuncSetAttribute(hmma_gemm<false>, cudaFuncAttributeMaxDynamicSharedMemorySize, gemm_smem);
        cudaFuncSetAttribute(hmma_gemm<true>,  cudaFuncAttributeMaxDynamicSharedMemorySize, gemm_smem);
        once = 1;
    }

    // ordered so the 6th launch (ncu -s 5 -c 1 capture) is the QKV GEMM
    cvt_split<<<4096, 256>>>(hidden, px2, 10, (long long)4096*1024/4, 0);
    cvt_split<<<1024, 256>>>(Wq, pw2,                     10, (long long)1024*1024/4, 0);
    cvt_split<<<1024, 256>>>(Wk, pw2 + (size_t)1024*2048, 10, (long long)1024*1024/4, 0);
    cvt_split<<<1024, 256>>>(Wv, pw2 + (size_t)2048*2048, 10, (long long)1024*1024/4, 0);
    bias_concat<<<12, 256>>>(bq, bk, bv);

    // QKV (bf16 3-term) -> fp16 split planes   [6th launch]
    hmma_gemm<false><<<dim3(24, 32, 1), 256, gemm_smem>>>(
        px2, 2048, 0, pw2, 2048, 0, nullptr, 0, 0, 1024, 1);

    cvt_split<<<1024, 256>>>(Wc, pwc2, 10, (long long)1024*1024/4, 0);
    cvt_split<<<64,   256>>>(pt, ppt2,  6, (long long)1024*64/4,   1);
    c2p_kernel<<<dim3(BH, 4), 256>>>(pt);

    // P2C (fp16 3-term) -> bf16
    hmma_gemm<true><<<dim3(16, 8, BH), 256, gemm_smem>>>(
        ppt2, 128, 0, pk2, 128, (long long)S_LEN*128,
        pp2cb, S_LEN, (long long)NPOS*S_LEN, 64, 2);

    flash_attn<<<dim3(S_LEN/128, BH), 256, FLASH_SMEM_BYTES>>>();

    // c_proj (bf16 3-term)
    hmma_gemm<false><<<dim3(8, 32, 1), 256, gemm_smem>>>(
        pao2, 2048, 0, pwc2, 2048, 0, out, DMODEL, 0, 1024, 0);
}